// round 17
// baseline (speedup 1.0000x reference)
#include <cuda_runtime.h>
#include <math.h>

// ---------------- problem constants ----------------
#define H_IMG 110
#define W_IMG 110
#define NPIX  (H_IMG * W_IMG)      // 12100
#define OHW   96
#define NOUT  (OHW * OHW)          // 9216
#define NBC   8                    // b*c = 2*4
#define NPLANE (NBC * 2)           // 16 (bc, t)
#define EPSF  1e-8f
#define SPEC_U 1.4142135623730951e-3f
#define TEMP_U 1.4142135623730951e-3f

// ---------------- scratch (static: no allocation allowed) ----------------
__device__ float  g_thr;
__device__ float2 g_acc[NBC * NOUT];      // pair-summed partials (S0, S1); reset each call
__device__ int    g_cnt[NBC * 18];        // per-tile arrival counter; reset each call

#define RED_THREADS 256
#define RED_PPT     4
#define RED_BLOCKS  ((NPLANE * NPIX + RED_THREADS * RED_PPT - 1) / (RED_THREADS * RED_PPT)) // 190
__device__ float g_part[RED_BLOCKS][3];
__device__ unsigned int g_ticket = 0;

__device__ __forceinline__ int wcount(int i) {   // #windows covering index i
    int lo = i - 14; if (lo < 0) lo = 0;
    int hi = i;      if (hi > 95) hi = 95;
    return hi - lo + 1;
}

__device__ __forceinline__ float warp_redf(float v) {
    #pragma unroll
    for (int o = 16; o > 0; o >>= 1) v += __shfl_down_sync(0xffffffffu, v, o);
    return v;
}
__device__ __forceinline__ double warp_redd(double v) {
    #pragma unroll
    for (int o = 16; o > 0; o >>= 1) v += __shfl_down_sync(0xffffffffu, v, o);
    return v;
}

// log(fl(1+x))/2 via atanh form; rel err ~4e-7
__device__ __forceinline__ float log1p_half(float x) {
    float u   = 1.0f + x;
    float xp  = u - 1.0f;        // exact (u in [1,2])
    float up1 = u + 1.0f;
    float ri;
    asm("rcp.approx.f32 %0, %1;" : "=f"(ri) : "f"(up1));
    float z  = xp * ri;          // z in [0, 1/3]
    float z2 = z * z;
    float p  = fmaf(z2, 0.0909090909f, 0.1111111111f);
    p = fmaf(p, z2, 0.1428571429f);
    p = fmaf(p, z2, 0.2f);
    p = fmaf(p, z2, 0.3333333333f);
    p = fmaf(p, z2, 1.0f);
    return z * p;
}

// invspat = 7/(d^2+7); constexpr folds to an immediate after full unroll
__host__ __device__ constexpr float inv_v(int dy, int dx) {
    return 7.0f / (float)((dy - 7) * (dy - 7) + (dx - 7) * (dx - 7) + 7);
}

// ---------------- pass 1: thr reduction (ticket, no spins) ----------------
__global__ __launch_bounds__(RED_THREADS)
void reduce_kernel(const float* __restrict__ pfg)
{
    const int idx0 = (blockIdx.x * blockDim.x + threadIdx.x) * RED_PPT;
    float c = 0.f, s = 0.f, s2 = 0.f;

    if (idx0 < NPLANE * NPIX) {    // NPIX % 4 == 0: quad never crosses plane edge
        float4 f = *(const float4*)(pfg + idx0);
        #pragma unroll
        for (int j = 0; j < 4; ++j) {
            float vpf = j == 0 ? f.x : j == 1 ? f.y : j == 2 ? f.z : f.w;
            if (vpf >= EPSF) {
                int pix = (idx0 + j) % NPIX;
                int h = pix / W_IMG, w = pix - h * W_IMG;
                float mult = (float)(wcount(h) * wcount(w));
                c  += mult;
                s  += mult * vpf;
                s2 += mult * vpf * vpf;
            }
        }
    }

    __shared__ float  smf[8][3];
    __shared__ double smd[8][3];
    __shared__ int isLast;
    const int tid = threadIdx.x, warp = tid >> 5, lane = tid & 31;
    c = warp_redf(c); s = warp_redf(s); s2 = warp_redf(s2);
    if (lane == 0) { smf[warp][0] = c; smf[warp][1] = s; smf[warp][2] = s2; }
    __syncthreads();
    if (tid == 0) {
        float C = 0, S = 0, S2 = 0;
        #pragma unroll
        for (int w = 0; w < 8; w++) { C += smf[w][0]; S += smf[w][1]; S2 += smf[w][2]; }
        g_part[blockIdx.x][0] = C; g_part[blockIdx.x][1] = S; g_part[blockIdx.x][2] = S2;
        __threadfence();
        unsigned t = atomicAdd(&g_ticket, 1u);
        isLast = (t == gridDim.x - 1);
    }
    __syncthreads();
    if (isLast) {                 // last ARRIVER finalizes; nobody waits
        __threadfence();
        double cc = 0, ss = 0, ss2 = 0;
        for (int i = tid; i < RED_BLOCKS; i += RED_THREADS) {   // fixed order
            cc  += (double)g_part[i][0];
            ss  += (double)g_part[i][1];
            ss2 += (double)g_part[i][2];
        }
        cc = warp_redd(cc); ss = warp_redd(ss); ss2 = warp_redd(ss2);
        if (lane == 0) { smd[warp][0] = cc; smd[warp][1] = ss; smd[warp][2] = ss2; }
        __syncthreads();
        if (tid == 0) {
            double C = 0, S = 0, S2 = 0;
            #pragma unroll
            for (int w = 0; w < 8; w++) { C += smd[w][0]; S += smd[w][1]; S2 += smd[w][2]; }
            double m = S / C, m2 = S2 / C;
            g_thr = (float)(2.0 * sqrt(m2 - m * m) / 5.0);
            g_ticket = 0;     // reset for next graph replay
        }
    }
}

// ---------------- pass 2: main kernel (no spins anywhere) ----------------
// one (bc,t) plane per CTA; tile 32x16 outputs; 256 threads x 2 outputs each
#define TOX 32
#define TOY 16
#define SMW (TOX + 14)    // 46
#define SMH (TOY + 14)    // 30

// staged element q = (d = pc-pf, e = pc-pd, pf_or_NaN, R)
// staged row RR serves outputs o in [OMIN, OMAX]; dy = RR - o (compile-time)
template<int RR, int OMIN, int OMAX>
__device__ __forceinline__ void do_row(const float4* __restrict__ rq,
                                       const float* ms, const float* mt,
                                       const float* lo, const float* hi,
                                       float* S0, float* S1)
{
    #pragma unroll
    for (int dx = 0; dx < 15; ++dx) {
        float4 q = rq[dx];
        float val  = q.z - q.y;             // pf - (pc - pd) = pd + pf - pc (1 ulp)
        float Rval = q.w * val;             // shared across outputs
        #pragma unroll
        for (int o = OMIN; o <= OMAX; ++o) {
            bool pass = (fabsf(q.x) < ms[o]) & (fabsf(q.y) < mt[o]) &
                        (q.z > lo[o]) & (q.z < hi[o]);      // NaN -> false
            if (pass) {
                S0[o] = fmaf(q.w,  inv_v(RR - o, dx), S0[o]);  // FFMA-imm
                S1[o] = fmaf(Rval, inv_v(RR - o, dx), S1[o]);  // FFMA-imm
            }
        }
    }
}

__global__ __launch_bounds__(256, 2)
void starfm_kernel(const float* __restrict__ pcg,
                   const float* __restrict__ pfg,
                   const float* __restrict__ pdg,
                   float* __restrict__ out)
{
    __shared__ float4 Sq[SMH][SMW];
    __shared__ int    sh_old;

    const int pz  = blockIdx.z;           // plane = bc*2 + t
    const int bc  = pz >> 1;
    const int ty0 = blockIdx.y * TOY;
    const int tx0 = blockIdx.x * TOX;
    const int tx  = threadIdx.x, ty = threadIdx.y;   // block (32, 8)
    const int tid = ty * 32 + tx;
    const int row0 = 2 * ty;
    const int tileslot = (bc * 6 + blockIdx.y) * 3 + blockIdx.x;      // 0..143

    // ---- stage (d, e, pf_nan, R) ----
    const float* pcp = pcg + (size_t)pz * NPIX;
    const float* pfp = pfg + (size_t)pz * NPIX;
    const float* pdp = pdg + (size_t)bc * NPIX;

    // other-plane center spec/temp (LDGs overlap staging)
    const int oz = pz ^ 1;
    float osp[2], otp[2];
    #pragma unroll
    for (int o = 0; o < 2; ++o) {
        int cg = (ty0 + row0 + o + 7) * W_IMG + (tx0 + tx + 7);
        float c2 = pcg[(size_t)oz * NPIX + cg];
        float f2 = pfg[(size_t)oz * NPIX + cg];
        float d2 = pdp[cg];
        osp[o] = fabsf(c2 - f2);
        otp[o] = fabsf(c2 - d2);
    }

    for (int i = tid; i < SMH * SMW; i += 256) {
        int r  = i / SMW;
        int cl = i - r * SMW;
        int g  = (ty0 + r) * W_IMG + (tx0 + cl);
        float vpc = pcp[g];
        float vpf = pfp[g];
        float vpd = pdp[g];
        float d = vpc - vpf;            // true pf: spec = |d| exact
        float e = vpc - vpd;
        float G = 4.0f * (log1p_half(fabsf(d)) * log1p_half(fabsf(e)));
        float R;
        asm("rcp.approx.f32 %0, %1;" : "=f"(R) : "f"(G + EPSF));
        float pfn = (vpf >= EPSF) ? vpf : __int_as_float(0x7fffffff);  // NaN
        Sq[r][cl] = make_float4(d, e, pfn, R);
    }
    __syncthreads();

    const float thr = g_thr;    // stream-ordered after reduce_kernel

    // center thresholds: own-plane from smem (true d/e), other-plane from regs
    float ms[2], mt[2], lo[2], hi[2];
    #pragma unroll
    for (int o = 0; o < 2; ++o) {
        float4 qc = Sq[row0 + o + 7][tx + 7];
        ms[o] = fmaxf(fabsf(qc.x), osp[o]) + SPEC_U;
        mt[o] = fmaxf(fabsf(qc.y), otp[o]) + TEMP_U;
        float pfc = qc.z;                    // may be NaN -> all elements fail
        lo[o] = pfc - thr;
        hi[o] = pfc + thr;
    }

    // ---- window loop ----
    float S0[2] = {0.f, 0.f};
    float S1[2] = {0.f, 0.f};

    #define ROW(RR, A, B) do_row<RR, A, B>(&Sq[row0 + RR][tx], ms, mt, lo, hi, S0, S1);
    ROW(0,  0, 0)
    ROW(1,  0, 1)  ROW(2,  0, 1)  ROW(3,  0, 1)  ROW(4,  0, 1)
    ROW(5,  0, 1)  ROW(6,  0, 1)  ROW(7,  0, 1)  ROW(8,  0, 1)
    ROW(9,  0, 1)  ROW(10, 0, 1)  ROW(11, 0, 1)  ROW(12, 0, 1)
    ROW(13, 0, 1)  ROW(14, 0, 1)
    ROW(15, 1, 1)
    #undef ROW

    // ---- arrival-counter combine (no waiting; second arriver finalizes) ----
    // Exactly 2 contributors per output; float add is commutative, so the
    // accumulated (S0,S1) are bitwise deterministic regardless of order.
    const int ox = tx0 + tx;
    int oi0 = bc * NOUT + (ty0 + row0) * OHW + ox;
    atomicAdd(&g_acc[oi0].x,       S0[0]);
    atomicAdd(&g_acc[oi0].y,       S1[0]);
    atomicAdd(&g_acc[oi0 + OHW].x, S0[1]);
    atomicAdd(&g_acc[oi0 + OHW].y, S1[1]);
    __threadfence();
    __syncthreads();
    if (tid == 0) sh_old = atomicAdd(&g_cnt[tileslot], 1);
    __syncthreads();
    if (sh_old == 1) {                 // this CTA arrived second: finalize tile
        __threadfence();
        #pragma unroll
        for (int o = 0; o < 2; ++o) {
            int oi = oi0 + o * OHW;
            float2 a = g_acc[oi];
            out[oi] = a.y / (a.x + EPSF);
            g_acc[oi] = make_float2(0.f, 0.f);   // reset for next replay
        }
        __syncthreads();               // all resets done before counter reset
        if (tid == 0) g_cnt[tileslot] = 0;       // reset for next replay
    }
}

// ---------------- launch ----------------
extern "C" void kernel_launch(void* const* d_in, const int* in_sizes, int n_in,
                              void* d_out, int out_size)
{
    const float* pc = (const float*)d_in[0];   // prior_coarse (2,4,2,110,110)
    const float* pf = (const float*)d_in[1];   // prior_fine   (2,4,2,110,110)
    const float* pd = (const float*)d_in[2];   // pred_coarse  (2,4,110,110)
    float* out = (float*)d_out;                // (2,4,96,96)

    reduce_kernel<<<RED_BLOCKS, RED_THREADS>>>(pf);

    dim3 grid(OHW / TOX, OHW / TOY, NPLANE);   // (3, 6, 16) = 288 CTAs
    dim3 block(32, 8);
    starfm_kernel<<<grid, block>>>(pc, pf, pd, out);
}